// round 15
// baseline (speedup 1.0000x reference)
#include <cuda_runtime.h>
#include <cuda_fp16.h>
#include <cstdint>
#include <math.h>

#define BATCH 2
#define TSEQ  4096
#define NH    16
#define HD    64
#define CEMB  1024
#define MROWS (BATCH*TSEQ)          // 8192
#define SCALE2 0.1803368801111204f  // (1/8) * log2(e)

// ---------------- scratch (fp16 operands) --------------------------------------
__device__ __half g_x16[(size_t)MROWS*CEMB];
__device__ __half g_y16[(size_t)MROWS*CEMB];
__device__ __half g_wq16[(size_t)3*CEMB*CEMB];   // [N,K] K-major
__device__ __half g_wp16[(size_t)CEMB*CEMB];
__device__ __half g_q16[(size_t)BATCH*NH*TSEQ*HD];
__device__ __half g_k16[(size_t)BATCH*NH*TSEQ*HD];
__device__ __half g_v16[(size_t)BATCH*NH*TSEQ*HD];

// ---------------- PTX helpers --------------------------------------------------
__device__ __forceinline__ uint32_t smem_u32(const void* p) {
    uint32_t a;
    asm("{ .reg .u64 t; cvta.to.shared.u64 t, %1; cvt.u32.u64 %0, t; }"
        : "=r"(a) : "l"(p));
    return a;
}
__device__ __forceinline__ void cpasync16(uint32_t saddr, const void* g) {
    asm volatile("cp.async.cg.shared.global [%0], [%1], 16;"
                 :: "r"(saddr), "l"(g) : "memory");
}
#define CP_COMMIT() asm volatile("cp.async.commit_group;" ::: "memory")
#define CP_WAIT2()  asm volatile("cp.async.wait_group 2;" ::: "memory")
#define CP_WAIT1()  asm volatile("cp.async.wait_group 1;" ::: "memory")
#define CP_WAIT0()  asm volatile("cp.async.wait_group 0;" ::: "memory")

__device__ __forceinline__ void ldmx4(uint32_t* r, uint32_t addr) {
    asm volatile("ldmatrix.sync.aligned.m8n8.x4.shared.b16 {%0,%1,%2,%3}, [%4];"
        : "=r"(r[0]), "=r"(r[1]), "=r"(r[2]), "=r"(r[3]) : "r"(addr));
}
__device__ __forceinline__ void ldmx2(uint32_t* r, uint32_t addr) {
    asm volatile("ldmatrix.sync.aligned.m8n8.x2.shared.b16 {%0,%1}, [%2];"
        : "=r"(r[0]), "=r"(r[1]) : "r"(addr));
}
__device__ __forceinline__ void ldmx4t(uint32_t* r, uint32_t addr) {
    asm volatile("ldmatrix.sync.aligned.m8n8.x4.trans.shared.b16 {%0,%1,%2,%3}, [%4];"
        : "=r"(r[0]), "=r"(r[1]), "=r"(r[2]), "=r"(r[3]) : "r"(addr));
}
__device__ __forceinline__ void mma16816(float* d, const uint32_t* a,
                                         const uint32_t* b) {
    asm volatile(
        "mma.sync.aligned.m16n8k16.row.col.f32.f16.f16.f32 "
        "{%0,%1,%2,%3}, {%4,%5,%6,%7}, {%8,%9}, {%0,%1,%2,%3};"
        : "+f"(d[0]), "+f"(d[1]), "+f"(d[2]), "+f"(d[3])
        : "r"(a[0]), "r"(a[1]), "r"(a[2]), "r"(a[3]), "r"(b[0]), "r"(b[1]));
}
// f16-accumulator HMMA (throughput experiment)
__device__ __forceinline__ void mma16816h(uint32_t* d, const uint32_t* a,
                                          const uint32_t* b) {
    asm volatile(
        "mma.sync.aligned.m16n8k16.row.col.f16.f16.f16.f16 "
        "{%0,%1}, {%2,%3,%4,%5}, {%6,%7}, {%0,%1};"
        : "+r"(d[0]), "+r"(d[1])
        : "r"(a[0]), "r"(a[1]), "r"(a[2]), "r"(a[3]), "r"(b[0]), "r"(b[1]));
}

__device__ __forceinline__ float ex2(float x) {
    float r;
    asm("ex2.approx.ftz.f32 %0, %1;" : "=f"(r) : "f"(x));
    return r;
}
__device__ __forceinline__ uint32_t ex2h2(uint32_t x) {
    uint32_t r;
    asm("ex2.approx.f16x2 %0, %1;" : "=r"(r) : "r"(x));
    return r;
}
__device__ __forceinline__ float2 h2f2(uint32_t u) {
    __half2 h = *(__half2*)&u;
    return __half22float2(h);
}
__device__ __forceinline__ uint32_t packh(float x, float y) {
    __half2 t = __floats2half2_rn(x, y);
    return *(uint32_t*)&t;
}

// ---------------- merged conversion kernel --------------------------------------
__global__ void conv_all(const float* __restrict__ x,
                         const float* __restrict__ wq,
                         const float* __restrict__ wp)
{
    __shared__ float t[32][33];
    int bid = blockIdx.x;
    if (bid < 8192) {
        int i = (bid * 256 + threadIdx.x) * 4;
        float4 v = *(const float4*)&x[i];
        uint2 p;
        p.x = packh(v.x, v.y);
        p.y = packh(v.z, v.w);
        *(uint2*)&g_x16[i] = p;
        return;
    }
    const float* w;
    __half* dT;
    int n0, k0, N;
    if (bid < 11264) {
        int idx = bid - 8192;
        w = wq; dT = g_wq16; N = 3 * CEMB;
        n0 = (idx % 96) * 32; k0 = (idx / 96) * 32;
    } else {
        int idx = bid - 11264;
        w = wp; dT = g_wp16; N = CEMB;
        n0 = (idx & 31) * 32; k0 = (idx >> 5) * 32;
    }
    int tx = threadIdx.x & 31, ty = threadIdx.x >> 5;
    for (int r = ty; r < 32; r += 8)
        t[r][tx] = w[(size_t)(k0 + r) * N + n0 + tx];
    __syncthreads();
    for (int r = ty; r < 32; r += 8)
        dT[(size_t)(n0 + r) * CEMB + k0 + tx] = __float2half_rn(t[tx][r]);
}

// ---------------- fp16 GEMM, 3-stage cp.async, 2 CTAs/SM -----------------------
// MODE 0: fp32 accumulators. MODE 1: f16 accumulators per K=64 chunk,
// promoted to fp32 once per k-tile (throughput experiment).
#define BK    64
#define ROWB  144
#define MATB  (128*ROWB)            // 18432
#define STAGEB (2*MATB)             // 36864
#define GSMEM (3*STAGEB)            // 110592

template <int MODE>
__global__ __launch_bounds__(256, 2)
void gemm_mma(const float* __restrict__ bias, float* __restrict__ out)
{
    extern __shared__ __align__(16) char sm[];
    uint32_t smb = smem_u32(sm);

    const __half* A16 = (MODE == 0) ? g_x16 : g_y16;
    const __half* B16 = (MODE == 0) ? g_wq16 : g_wp16;

    int tid = threadIdx.x;
    int wid = tid >> 5, lane = tid & 31;
    int wm = wid >> 2, wn = wid & 3;
    int mBase = blockIdx.y * 128, nBase = blockIdx.x * 128;

    float acc[4][4][4];
#pragma unroll
    for (int mi = 0; mi < 4; mi++)
#pragma unroll
        for (int ni = 0; ni < 4; ni++)
#pragma unroll
            for (int q = 0; q < 4; q++) acc[mi][ni][q] = 0.f;

    auto load_stage = [&](int st, int kt) {
        int k0 = kt * BK;
        uint32_t sb = smb + st * STAGEB;
#pragma unroll
        for (int c = tid; c < 1024; c += 256) {
            int row = c >> 3, ch = c & 7;
            cpasync16(sb + row * ROWB + ch * 16,
                      A16 + (size_t)(mBase + row) * CEMB + k0 + ch * 8);
        }
#pragma unroll
        for (int c = tid; c < 1024; c += 256) {
            int row = c >> 3, ch = c & 7;
            cpasync16(sb + MATB + row * ROWB + ch * 16,
                      B16 + (size_t)(nBase + row) * CEMB + k0 + ch * 8);
        }
    };

    int g = lane >> 3, w = lane & 7;
    uint32_t a_row = (wm * 64 + ((g & 1) << 3) + w) * ROWB;
    uint32_t b_row = (wn * 32 + w) * ROWB;
    uint32_t ka_off = ((g >> 1) << 3) * 2;
    uint32_t kb_off = ((g & 1) << 3) * 2;

    load_stage(0, 0); CP_COMMIT();
    load_stage(1, 1); CP_COMMIT();

    for (int kt = 0; kt < 16; kt++) {
        if (kt < 15) CP_WAIT1(); else CP_WAIT0();
        __syncthreads();
        if (kt + 2 < 16) { load_stage((kt + 2) % 3, kt + 2); CP_COMMIT(); }

        uint32_t bA = smb + (kt % 3) * STAGEB;
        uint32_t bB = bA + MATB;

        if (MODE == 0) {
#pragma unroll
            for (int ks = 0; ks < 4; ks++) {
                uint32_t ka = ks * 32 + ka_off;
                uint32_t kb = ks * 32 + kb_off;
                uint32_t ah[4][4], bh[4][2];
#pragma unroll
                for (int mi = 0; mi < 4; mi++)
                    ldmx4(ah[mi], bA + a_row + mi * 16 * ROWB + ka);
#pragma unroll
                for (int ni = 0; ni < 4; ni++)
                    ldmx2(bh[ni], bB + b_row + ni * 8 * ROWB + kb);
#pragma unroll
                for (int mi = 0; mi < 4; mi++)
#pragma unroll
                    for (int ni = 0; ni < 4; ni++)
                        mma16816(acc[mi][ni], ah[mi], bh[ni]);
            }
        } else {
            // f16 accumulation over this K=64 chunk, then promote
            uint32_t bfr[4][4][2];
#pragma unroll
            for (int ks = 0; ks < 4; ks++)
#pragma unroll
                for (int ni = 0; ni < 4; ni++)
                    ldmx2(bfr[ks][ni],
                          bB + b_row + ni * 8 * ROWB + ks * 32 + kb_off);
#pragma unroll
            for (int mi = 0; mi < 4; mi++) {
                uint32_t hacc[4][2];
#pragma unroll
                for (int ni = 0; ni < 4; ni++) {
                    hacc[ni][0] = 0u; hacc[ni][1] = 0u;
                }
#pragma unroll
                for (int ks = 0; ks < 4; ks++) {
                    uint32_t ah[4];
                    ldmx4(ah, bA + a_row + mi * 16 * ROWB + ks * 32 + ka_off);
#pragma unroll
                    for (int ni = 0; ni < 4; ni++)
                        mma16816h(hacc[ni], ah, bfr[ks][ni]);
                }
#pragma unroll
                for (int ni = 0; ni < 4; ni++) {
                    float2 lo = h2f2(hacc[ni][0]);
                    float2 hi = h2f2(hacc[ni][1]);
                    acc[mi][ni][0] += lo.x; acc[mi][ni][1] += lo.y;
                    acc[mi][ni][2] += hi.x; acc[mi][ni][3] += hi.y;
                }
            }
        }
        __syncthreads();
    }

    int r_in = lane >> 2, c_in = (lane & 3) * 2;
#pragma unroll
    for (int mi = 0; mi < 4; mi++) {
#pragma unroll
        for (int half = 0; half < 2; half++) {
            int m = mBase + wm * 64 + mi * 16 + r_in + half * 8;
#pragma unroll
            for (int ni = 0; ni < 4; ni++) {
                int n = nBase + wn * 32 + ni * 8 + c_in;
                float v0 = acc[mi][ni][half * 2 + 0] + bias[n];
                float v1 = acc[mi][ni][half * 2 + 1] + bias[n + 1];
                if (MODE == 0) {
                    int b = m >> 12, t = m & 4095;
                    int sect = n >> 10, cc = n & 1023;
                    int head = cc >> 6, d0 = cc & 63;
                    size_t off = (((size_t)(b * NH + head)) * TSEQ + t) * HD + d0;
                    __half* dst = (sect == 0) ? g_q16 : (sect == 1) ? g_k16 : g_v16;
                    *(uint32_t*)&dst[off] = packh(v0, v1);
                } else {
                    *(float2*)&out[(size_t)m * CEMB + n] = make_float2(v0, v1);
                }
            }
        }
    }
}

// ---------------- fp16 HMMA block-sparse flash attention -----------------------
#define SMQ    0                            // 9216
#define SBA    9216
#define SLB    46080
#define SBGK   101376
#define SLAB   9216
#define SLABW  12288
#define SMRG   9216
#define MERGE_B 4352
#define ATTN_SM (SLAB + 8*SLABW)            // 107520

// MODE: 0 = fully valid, 1 = upper, 2 = lower, 3 = general
template <int NNI, int MODE>
__device__ __forceinline__ void dense_block(
    const uint32_t (&qf)[4][4], uint32_t kst, uint32_t vst, int lane, int rblk,
    int colbase, int i0, int jb, float (&oacc)[8][4], float (&m)[2], float (&l)[2])
{
    const int NKK = NNI / 2;
    int g = lane >> 3, w = lane & 7;
    uint32_t kboff = (g & 1) * 16;

    unsigned skipmask = 0;
    if (MODE == 1) {
#pragma unroll
        for (int ni = 0; ni < NNI; ni++)
            if (colbase + ni * 8 + 7 < rblk) skipmask |= 1u << ni;
    } else if (MODE == 2) {
#pragma unroll
        for (int ni = 0; ni < NNI; ni++)
            if (colbase + ni * 8 > rblk + 15) skipmask |= 1u << ni;
    }

    float sacc[NNI][4];
#pragma unroll
    for (int ni = 0; ni < NNI; ni++)
#pragma unroll
        for (int q = 0; q < 4; q++) sacc[ni][q] = 0.f;

#pragma unroll
    for (int ks = 0; ks < 4; ks++) {
#pragma unroll
        for (int ni = 0; ni < NNI; ni++) {
            if ((skipmask >> ni) & 1) continue;
            uint32_t kb2[2];
            ldmx2(kb2, kst + (colbase + ni * 8 + w) * 144 + kboff + ks * 32);
            mma16816(sacc[ni], qf[ks], kb2);
        }
    }

    int c0 = (lane & 3) * 2;
    float mb0 = -1e30f, mb1 = -1e30f;
#pragma unroll
    for (int ni = 0; ni < NNI; ni++) {
        if ((skipmask >> ni) & 1) continue;
        int jB = jb + ni * 8 + c0;
#pragma unroll
        for (int q = 0; q < 4; q++) {
            int jj = jB + (q & 1);
            int ii = (q < 2) ? i0 : i0 + 8;
            bool ok;
            if (MODE == 0) ok = true;
            else if (MODE == 1) ok = (ii - jj) <= 256;
            else if (MODE == 2) ok = jj <= ii;
            else {
                int diff = ii - jj;
                ok = diff >= 0 && (diff < 256 || (diff & 127) == 0 || jj < 16);
            }
            sacc[ni][q] = ok ? sacc[ni][q] * SCALE2 : -1e30f;
        }
        mb0 = fmaxf(mb0, fmaxf(sacc[ni][0], sacc[ni][1]));
        mb1 = fmaxf(mb1, fmaxf(sacc[ni][2], sacc[ni][3]));
    }
    mb0 = fmaxf(mb0, __shfl_xor_sync(0xffffffffu, mb0, 1));
    mb0 = fmaxf(mb0, __shfl_xor_sync(0xffffffffu, mb0, 2));
    mb1 = fmaxf(mb1, __shfl_xor_sync(0xffffffffu, mb1, 1));
    mb1 = fmaxf(mb1, __shfl_xor_sync(0xffffffffu, mb1, 2));

    float mn0 = fmaxf(fmaxf(m[0], mb0), -1e28f);
    float mn1 = fmaxf(fmaxf(m[1], mb1), -1e28f);
    bool up = __any_sync(0xffffffffu, (mn0 > m[0]) || (mn1 > m[1]));
    float cs0 = 1.f, cs1 = 1.f;
    if (up) { cs0 = ex2(m[0] - mn0); cs1 = ex2(m[1] - mn1); }

    uint32_t pp[NNI][2];
    float ls0 = 0.f, ls1 = 0.f;
#pragma unroll
    for (int ni = 0; ni < NNI; ni++) {
        if ((skipmask >> ni) & 1) { pp[ni][0] = 0u; pp[ni][1] = 0u; continue; }
        uint32_t a0 = packh(sacc[ni][0] - mn0, sacc[ni][1] - mn0);
        uint32_t a1 = packh(sacc[ni][2] - mn1, sacc[ni][3] - mn1);
        uint32_t p0 = ex2h2(a0), p1 = ex2h2(a1);
        pp[ni][0] = p0; pp[ni][1] = p1;
        float2 f0 = h2f2(p0), f1 = h2f2(p1);
        ls0 += f0.x + f0.y; ls1 += f1.x + f1.y;
    }
    ls0 += __shfl_xor_sync(0xffffffffu, ls0, 1);
    ls0 += __shfl_xor_sync(0xffffffffu, ls0, 2);
    ls1 += __shfl_xor_sync(0xffffffffu, ls1, 1);
    ls1 += __shfl_xor_sync(0xffffffffu, ls1, 2);
    if (up) {
        l[0] = l[0] * cs0 + ls0;
        l[1] = l[1] * cs1 + ls1;
#pragma unroll
        for (int nd = 0; nd < 8; nd++) {
            oacc[nd][0] *= cs0; oacc[nd][1] *= cs0;
            oacc[nd][2] *= cs1; oacc[nd][3] *= cs1;
        }
    } else {
        l[0] += ls0; l[1] += ls1;
    }
    m[0] = mn0; m[1] = mn1;

    int jrow = ((g & 1) << 3) + w;
    int dcol = (g >> 1) * 16;
#pragma unroll
    for (int kk = 0; kk < NKK; kk++) {
        if (((skipmask >> (2 * kk)) & 3u) == 3u) continue;
        uint32_t pa[4] = { pp[2*kk][0], pp[2*kk][1], pp[2*kk+1][0], pp[2*kk+1][1] };
#pragma unroll
        for (int gv = 0; gv < 2; gv++) {
            uint32_t vh4[2][4];
#pragma unroll
            for (int u = 0; u < 2; u++) {
                int nd2 = gv * 2 + u;
                ldmx4t(vh4[u], vst + (colbase + kk * 16 + jrow) * 144 + nd2 * 32 + dcol);
            }
#pragma unroll
            for (int u = 0; u < 2; u++) {
                int nd2 = gv * 2 + u;
                mma16816(oacc[nd2 * 2],     pa, vh4[u]);
                mma16816(oacc[nd2 * 2 + 1], pa, vh4[u] + 2);
            }
        }
    }
}

__global__ __launch_bounds__(256, 2)
void attn_mma()
{
    extern __shared__ __align__(16) char sm[];
    uint32_t smb = smem_u32(sm);
    int tid = threadIdx.x, lane = tid & 31, wid = tid >> 5;
    int rg = wid >> 1, ch2 = wid & 1;
    int qt = (gridDim.x - 1) - blockIdx.x;
    int qb = qt >> 1, s = qt & 1;
    int bh = blockIdx.y;

    auto stage_rows = [&](uint32_t dst, const __half* src, int nrows) {
        for (int c = tid; c < nrows * 8; c += 256) {
            int row = c >> 3, ch = c & 7;
            cpasync16(dst + row * 144 + ch * 16, src + (size_t)row * HD + ch * 8);
        }
    };
    size_t hb = (size_t)bh * TSEQ * HD;

    stage_rows(smb + SMQ, g_q16 + hb + (size_t)qt * 64 * HD, 64);

    float oacc[8][4];
#pragma unroll
    for (int nd = 0; nd < 8; nd++)
#pragma unroll
        for (int q = 0; q < 4; q++) oacc[nd][q] = 0.f;
    float m[2] = { -1e30f, -1e30f }, l[2] = { 0.f, 0.f };
    int lr0 = rg * 16;
    int rblk = s * 64 + lr0;
    int i0 = qt * 64 + lr0 + (lane >> 2);

    uint32_t qf[4][4];
    int gq = lane >> 3, wq_ = lane & 7;
    uint32_t qrow = smb + SMQ + (lr0 + ((gq & 1) << 3) + wq_) * 144 + (gq >> 1) * 16;

    if (qb >= 3) {
        stage_rows(smb + SBA,         g_k16 + hb + (size_t)(qb - 1) * 128 * HD, 128);
        stage_rows(smb + SBA + 18432, g_v16 + hb + (size_t)(qb - 1) * 128 * HD, 128);
        CP_COMMIT();
        int cminB = s ? 64 : 0, cntB = s ? 64 : 128;
        uint32_t bK = smb + SLB, bV = bK + (uint32_t)cntB * 144;
        stage_rows(bK, g_k16 + hb + ((size_t)(qb - 2) * 128 + cminB) * HD, cntB);
        stage_rows(bV, g_v16 + hb + ((size_t)(qb - 2) * 128 + cminB) * HD, cntB);
        CP_COMMIT();
        int cntC = s ? 128 : 64;
        uint32_t cK = bV + (uint32_t)cntB * 144, cV = cK + (uint32_t)cntC * 144;
        stage_rows(cK, g_k16 + hb + (size_t)qb * 128 * HD, cntC);
        stage_rows(cV, g_v16 + hb + (size_t)qb * 128 * HD, cntC);
        stage_rows(smb + SBGK,        g_k16 + hb, 16);
        stage_rows(smb + SBGK + 2304, g_v16 + hb, 16);
        CP_COMMIT();

        CP_WAIT2(); __syncthreads();
#pragma unroll
        for (int ks = 0; ks < 4; ks++) ldmx4(qf[ks], qrow + ks * 32);
        dense_block<8, 0>(qf, smb + SBA, smb + SBA + 18432, lane, rblk,
                          ch2 * 64, i0, (qb - 1) * 128 + ch2 * 64, oacc, m, l);
        CP_WAIT0(); __syncthreads();
        dense_block<8, 1>(qf, bK - (uint32_t)cminB * 144, bV - (uint32_t)cminB * 144,
                          lane, rblk, ch2 * 64, i0, (qb - 2) * 128 + ch2 * 64, oacc, m, l);
        dense_block<8, 2>(qf, cK, cV, lane, rblk,
                          ch2 * 64, i0, qb * 128 + ch2 * 64, oacc, m, l);
        if (ch2 == 0)
            dense_block<2, 0>(qf, smb + SBGK, smb + SBGK + 2304, lane, rblk,
                              0, i0, 0, oacc, m, l);
    } else {
        stage_rows(smb + SBA,         g_k16 + hb, 128);
        stage_rows(smb + SBA + 18432, g_v16 + hb, 128);
        CP_COMMIT();
        if (qb >= 1) {
            stage_rows(smb + SLB,         g_k16 + hb + (size_t)128 * HD, 128);
            stage_rows(smb + SLB + 18432, g_v16 + hb + (size_t)128 * HD, 128);
        }
        CP_COMMIT();
        if (qb >= 1) CP_WAIT1(); else CP_WAIT0();
        __syncthreads();
#pragma unroll
        for (int ks = 0; ks < 4; ks++) ldmx4(qf[ks], qrow + ks * 32);
        dense_block<8, 3>(qf, smb + SBA, smb + SBA + 18432, lane, rblk,
                          ch2 * 64, i0, ch2 * 64, oacc, m, l);
        if (qb >= 1) {
            CP_WAIT0();
            __syncthreads();
            if (qb >= 2) {
                stage_rows(smb + SBA,         g_k16 + hb + (size_t)256 * HD, 128);
                stage_rows(smb + SBA + 18432, g_v16 + hb + (size_t)256 * HD, 128);
                CP_COMMIT();
            }
            dense_block<8, 3>(qf, smb + SLB, smb + SLB + 18432, lane, rblk,
                              ch2 * 64, i0, 128 + ch2 * 64, oacc, m, l);
            if (qb >= 2) {
                CP_WAIT0(); __syncthreads();
                dense_block<8, 3>(qf, smb + SBA, smb + SBA + 18432, lane, rblk,
                                  ch2 * 64, i0, 256 + ch2 * 64, oacc, m, l);
            }
        }
    }

    // ---------- strided diagonals ----------
    int nkb = qb - 2;
    if (nkb > 0) {
        __syncthreads();
        uint32_t slab = smb + SLAB + wid * SLABW;
        int part = lane & 3, qr = lane >> 2;

        auto stage_kb = [&](int slot, int kb) {
            size_t rowbase = (size_t)kb * 128 + s * 64 + rg * 16;
            const __half* Ksrc = g_k16 + hb + rowbase * HD;
            const __half* Vsrc = g_v16 + hb + rowbase * HD;
            uint32_t base = slab + slot * 4096;
#pragma unroll
            for (int c = lane; c < 128; c += 32) {
                int row = c >> 3, ch = c & 7;
                cpasync16(base + row * 128 + ch * 16,
                          Ksrc + (size_t)row * HD + ch * 8);
                cpasync16(base + 2048 + row * 128 + ch * 16,
                          Vsrc + (size_t)row * HD + ch * 8);
            }
            CP_COMMIT();
        };

        int nexts = ch2;
#pragma unroll
        for (int st2 = 0; st2 < 3; st2++) {
            if (nexts < nkb) { stage_kb(st2, nexts); nexts += 2; }
        }

        int it = 0;
        for (int kb = ch2; kb < nkb; kb += 2, it++) {
            int ahead = (nexts - kb) >> 1;
            if (ahead >= 3) CP_WAIT2();
            else if (ahead == 2) CP_WAIT1();
            else CP_WAIT0();
            __syncwarp();

            uint32_t st = slab + (it % 3) * 4096;
#pragma unroll
            for (int h = 0; h < 2; h++) {
                int lr = qr + h * 8;
                int rowin128 = s * 64 + rg * 16 + lr;
                float sc;
                if (kb == 0 && rowin128 < 16) {
                    sc = -1e30f;
                } else {
                    uint32_t kaddr = st + lr * 128 + part * 32;
                    uint32_t qaddr = smb + SMQ + (rg * 16 + lr) * 144 + part * 32;
                    float sum = 0.f;
#pragma unroll
                    for (int seg = 0; seg < 2; seg++) {
                        uint32_t k4[4], q4[4];
                        asm volatile("ld.shared.v4.b32 {%0,%1,%2,%3}, [%4];"
                            : "=r"(k4[0]), "=r"(k4[1]), "=r"(k4[2]), "=r"(k4[3])
                            : "r"(kaddr + seg * 16));
                        asm volatile("ld.shared.v4.b32 {%0,%1,%2,%3}, [%4];"
                            : "=r"(q4[0]), "=r"(q4[1]), "=r"(q4[2]), "=r"(q4[3])
                            : "r"(qaddr + seg * 16));
#pragma unroll
                        for (int u = 0; u < 4; u++) {
                            float2 qf2 = h2f2(q4[u]), kf = h2f2(k4[u]);
                            sum += qf2.x * kf.x + qf2.y * kf.y;
                        }
                    }
                    sum += __shfl_xor_sync(0xffffffffu, sum, 1);
                    sum += __shfl_xor_sync(0xffffffffu, sum, 2);
                    sc = sum * SCALE2;
                }
                float mold = m[h];
                float mx = fmaxf(fmaxf(mold, sc), -1e28f);
                float p = ex2(sc - mx);
                if (__any_sync(0xffffffffu, mx > mold)) {
                    float cs = ex2(mold - mx);
                    l[h] = l[h] * cs + p;
                    m[h] = mx;
#pragma unroll
                    for (int nd = 0; nd < 8; nd++) {
                        oacc[nd][h * 2 + 0] *= cs;
                        oacc[nd][h * 2 + 1] *= cs;
                    }
                } else {
                    l[h] += p;
                }
                uint32_t vaddr = st + 2048 + lr * 128 + part * 4;
#pragma unroll
                for (int nd = 0; nd < 8; nd++) {
                    uint32_t vv;
                    asm volatile("ld.shared.b32 %0, [%1];"
                        : "=r"(vv) : "r"(vaddr + nd * 16));
                    float2 vf = h2f2(vv);
                    oacc[nd][h * 2 + 0] += p * vf.x;
                    oacc[nd][h * 2 + 1] += p * vf.y;
                }
            }

            if (nexts < nkb) {
                __syncwarp();
                stage_kb(it % 3, nexts);
                nexts += 2;
            }
        }
    }

    // pairwise split-softmax merge, then epilogue
    __syncthreads();
    {
        char* mb = sm + SMRG + wid * MERGE_B;
#pragma unroll
        for (int h = 0; h < 2; h++) {
            int row = (lane >> 2) + h * 8;
#pragma unroll
            for (int nd = 0; nd < 8; nd++) {
                int col = nd * 8 + (lane & 3) * 2;
                *(float2*)(mb + (row * 64 + col) * 4) =
                    make_float2(oacc[nd][h * 2], oacc[nd][h * 2 + 1]);
            }
            if ((lane & 3) == 0)
                *(float2*)(mb + 4096 + row * 8) = make_float2(m[h], l[h]);
        }
    }
    __syncthreads();
    if (ch2 == 0) {
        char* pb = sm + SMRG + (wid + 1) * MERGE_B;
        int b = bh >> 4, head = bh & 15;
#pragma unroll
        for (int h = 0; h < 2; h++) {
            int row = (lane >> 2) + h * 8;
            float2 ml = *(float2*)(pb + 4096 + row * 8);
            float mx = fmaxf(m[h], ml.x);
            float f0 = ex2(m[h] - mx), f1 = ex2(ml.x - mx);
            float L = l[h] * f0 + ml.y * f1;
            float inv = 1.f / L;
            int i = qt * 64 + rg * 16 + row;
            size_t row_off = ((size_t)(b * TSEQ + i)) * CEMB + head * HD;
#pragma unroll
            for (int nd = 0; nd < 8; nd++) {
                int col = nd * 8 + (lane & 3) * 2;
                float2 o1 = *(float2*)(pb + (row * 64 + col) * 4);
                float y0 = (oacc[nd][h * 2 + 0] * f0 + o1.x * f1) * inv;
                float y1 = (oacc[nd][h * 2 + 1] * f0 + o1.y * f1) * inv;
                *(uint32_t*)&g_y16[row_off + col] = packh(y0, y1);
            }
        }
    }
}

// ---------------- launch -------------------------------------------------------
extern "C" void kernel_launch(void* const* d_in, const int* in_sizes, int n_in,
                              void* d_out, int out_size)
{
    const float* x      = (const float*)d_in[0];
    const float* w_qkv  = (const float*)d_in[1];
    const float* b_qkv  = (const float*)d_in[2];
    const float* w_proj = (const float*)d_in[3];
    const float* b_proj = (const float*)d_in[4];
    float* out = (float*)d_out;

    cudaFuncSetAttribute(gemm_mma<0>,
                         cudaFuncAttributeMaxDynamicSharedMemorySize, GSMEM);
    cudaFuncSetAttribute(gemm_mma<1>,
                         cudaFuncAttributeMaxDynamicSharedMemorySize, GSMEM);
    cudaFuncSetAttribute(attn_mma,
                         cudaFuncAttributeMaxDynamicSharedMemorySize, ATTN_SM);

    conv_all<<<12288, 256>>>(x, w_qkv, w_proj);
    gemm_mma<0><<<dim3(3 * CEMB / 128, MROWS / 128), 256, GSMEM>>>(b_qkv, nullptr);
    attn_mma<<<dim3(TSEQ / 64, BATCH * NH), 256, ATTN_SM>>>();
    gemm_mma<1><<<dim3(CEMB / 128, MROWS / 128), 256, GSMEM>>>(b_proj, out);
}

// round 16
// speedup vs baseline: 1.0364x; 1.0364x over previous
#include <cuda_runtime.h>
#include <cuda_fp16.h>
#include <cstdint>
#include <math.h>

#define BATCH 2
#define TSEQ  4096
#define NH    16
#define HD    64
#define CEMB  1024
#define MROWS (BATCH*TSEQ)          // 8192
#define SCALE2 0.1803368801111204f  // (1/8) * log2(e)

// ---------------- scratch (fp16 operands) --------------------------------------
__device__ __half g_x16[(size_t)MROWS*CEMB];
__device__ __half g_y16[(size_t)MROWS*CEMB];
__device__ __half g_wq16[(size_t)3*CEMB*CEMB];   // [N,K] K-major
__device__ __half g_wp16[(size_t)CEMB*CEMB];
__device__ __half g_q16[(size_t)BATCH*NH*TSEQ*HD];
__device__ __half g_k16[(size_t)BATCH*NH*TSEQ*HD];
__device__ __half g_v16[(size_t)BATCH*NH*TSEQ*HD];

// ---------------- PTX helpers --------------------------------------------------
__device__ __forceinline__ uint32_t smem_u32(const void* p) {
    uint32_t a;
    asm("{ .reg .u64 t; cvta.to.shared.u64 t, %1; cvt.u32.u64 %0, t; }"
        : "=r"(a) : "l"(p));
    return a;
}
__device__ __forceinline__ void cpasync16(uint32_t saddr, const void* g) {
    asm volatile("cp.async.cg.shared.global [%0], [%1], 16;"
                 :: "r"(saddr), "l"(g) : "memory");
}
#define CP_COMMIT() asm volatile("cp.async.commit_group;" ::: "memory")
#define CP_WAIT2()  asm volatile("cp.async.wait_group 2;" ::: "memory")
#define CP_WAIT1()  asm volatile("cp.async.wait_group 1;" ::: "memory")
#define CP_WAIT0()  asm volatile("cp.async.wait_group 0;" ::: "memory")

__device__ __forceinline__ void ldmx4(uint32_t* r, uint32_t addr) {
    asm volatile("ldmatrix.sync.aligned.m8n8.x4.shared.b16 {%0,%1,%2,%3}, [%4];"
        : "=r"(r[0]), "=r"(r[1]), "=r"(r[2]), "=r"(r[3]) : "r"(addr));
}
__device__ __forceinline__ void ldmx2(uint32_t* r, uint32_t addr) {
    asm volatile("ldmatrix.sync.aligned.m8n8.x2.shared.b16 {%0,%1}, [%2];"
        : "=r"(r[0]), "=r"(r[1]) : "r"(addr));
}
__device__ __forceinline__ void ldmx4t(uint32_t* r, uint32_t addr) {
    asm volatile("ldmatrix.sync.aligned.m8n8.x4.trans.shared.b16 {%0,%1,%2,%3}, [%4];"
        : "=r"(r[0]), "=r"(r[1]), "=r"(r[2]), "=r"(r[3]) : "r"(addr));
}
__device__ __forceinline__ void mma16816(float* d, const uint32_t* a,
                                         const uint32_t* b) {
    asm volatile(
        "mma.sync.aligned.m16n8k16.row.col.f32.f16.f16.f32 "
        "{%0,%1,%2,%3}, {%4,%5,%6,%7}, {%8,%9}, {%0,%1,%2,%3};"
        : "+f"(d[0]), "+f"(d[1]), "+f"(d[2]), "+f"(d[3])
        : "r"(a[0]), "r"(a[1]), "r"(a[2]), "r"(a[3]), "r"(b[0]), "r"(b[1]));
}

__device__ __forceinline__ float ex2(float x) {
    float r;
    asm("ex2.approx.ftz.f32 %0, %1;" : "=f"(r) : "f"(x));
    return r;
}
__device__ __forceinline__ uint32_t ex2h2(uint32_t x) {
    uint32_t r;
    asm("ex2.approx.f16x2 %0, %1;" : "=r"(r) : "r"(x));
    return r;
}
__device__ __forceinline__ float2 h2f2(uint32_t u) {
    __half2 h = *(__half2*)&u;
    return __half22float2(h);
}
__device__ __forceinline__ uint32_t packh(float x, float y) {
    __half2 t = __floats2half2_rn(x, y);
    return *(uint32_t*)&t;
}

// ---------------- merged conversion kernel --------------------------------------
__global__ void conv_all(const float* __restrict__ x,
                         const float* __restrict__ wq,
                         const float* __restrict__ wp)
{
    __shared__ float t[32][33];
    int bid = blockIdx.x;
    if (bid < 8192) {
        int i = (bid * 256 + threadIdx.x) * 4;
        float4 v = *(const float4*)&x[i];
        uint2 p;
        p.x = packh(v.x, v.y);
        p.y = packh(v.z, v.w);
        *(uint2*)&g_x16[i] = p;
        return;
    }
    const float* w;
    __half* dT;
    int n0, k0, N;
    if (bid < 11264) {
        int idx = bid - 8192;
        w = wq; dT = g_wq16; N = 3 * CEMB;
        n0 = (idx % 96) * 32; k0 = (idx / 96) * 32;
    } else {
        int idx = bid - 11264;
        w = wp; dT = g_wp16; N = CEMB;
        n0 = (idx & 31) * 32; k0 = (idx >> 5) * 32;
    }
    int tx = threadIdx.x & 31, ty = threadIdx.x >> 5;
    for (int r = ty; r < 32; r += 8)
        t[r][tx] = w[(size_t)(k0 + r) * N + n0 + tx];
    __syncthreads();
    for (int r = ty; r < 32; r += 8)
        dT[(size_t)(n0 + r) * CEMB + k0 + tx] = __float2half_rn(t[tx][r]);
}

// ---------------- fp16 GEMM, 3-stage cp.async, 2 CTAs/SM, 1 barrier/iter ------
#define BK    64
#define ROWB  144
#define MATB  (128*ROWB)            // 18432
#define STAGEB (2*MATB)             // 36864
#define GSMEM (3*STAGEB)            // 110592

template <int MODE>
__global__ __launch_bounds__(256, 2)
void gemm_mma(const float* __restrict__ bias, float* __restrict__ out)
{
    extern __shared__ __align__(16) char sm[];
    uint32_t smb = smem_u32(sm);

    const __half* A16 = (MODE == 0) ? g_x16 : g_y16;
    const __half* B16 = (MODE == 0) ? g_wq16 : g_wp16;

    int tid = threadIdx.x;
    int wid = tid >> 5, lane = tid & 31;
    int wm = wid >> 2, wn = wid & 3;
    int mBase = blockIdx.y * 128, nBase = blockIdx.x * 128;

    float acc[4][4][4];
#pragma unroll
    for (int mi = 0; mi < 4; mi++)
#pragma unroll
        for (int ni = 0; ni < 4; ni++)
#pragma unroll
            for (int q = 0; q < 4; q++) acc[mi][ni][q] = 0.f;

    auto load_stage = [&](int st, int kt) {
        int k0 = kt * BK;
        uint32_t sb = smb + st * STAGEB;
#pragma unroll
        for (int c = tid; c < 1024; c += 256) {
            int row = c >> 3, ch = c & 7;
            cpasync16(sb + row * ROWB + ch * 16,
                      A16 + (size_t)(mBase + row) * CEMB + k0 + ch * 8);
        }
#pragma unroll
        for (int c = tid; c < 1024; c += 256) {
            int row = c >> 3, ch = c & 7;
            cpasync16(sb + MATB + row * ROWB + ch * 16,
                      B16 + (size_t)(nBase + row) * CEMB + k0 + ch * 8);
        }
    };

    int g = lane >> 3, w = lane & 7;
    uint32_t a_row = (wm * 64 + ((g & 1) << 3) + w) * ROWB;
    uint32_t b_row = (wn * 32 + w) * ROWB;
    uint32_t ka_off = ((g >> 1) << 3) * 2;
    uint32_t kb_off = ((g & 1) << 3) * 2;

    load_stage(0, 0); CP_COMMIT();
    load_stage(1, 1); CP_COMMIT();

    for (int kt = 0; kt < 16; kt++) {
        if (kt < 15) CP_WAIT1(); else CP_WAIT0();
        __syncthreads();
        // With 3 stages, writes to buffer (kt+2)%3 here conflict only with
        // reads from iteration kt-1, which the barrier above already orders.
        if (kt + 2 < 16) { load_stage((kt + 2) % 3, kt + 2); CP_COMMIT(); }

        uint32_t bA = smb + (kt % 3) * STAGEB;
        uint32_t bB = bA + MATB;

#pragma unroll
        for (int ks = 0; ks < 4; ks++) {
            uint32_t ka = ks * 32 + ka_off;
            uint32_t kb = ks * 32 + kb_off;
            uint32_t ah[4][4], bh[4][2];
#pragma unroll
            for (int mi = 0; mi < 4; mi++)
                ldmx4(ah[mi], bA + a_row + mi * 16 * ROWB + ka);
#pragma unroll
            for (int ni = 0; ni < 4; ni++)
                ldmx2(bh[ni], bB + b_row + ni * 8 * ROWB + kb);
#pragma unroll
            for (int mi = 0; mi < 4; mi++)
#pragma unroll
                for (int ni = 0; ni < 4; ni++)
                    mma16816(acc[mi][ni], ah[mi], bh[ni]);
        }
        // no trailing barrier: next iteration's top barrier provides ordering
    }

    int r_in = lane >> 2, c_in = (lane & 3) * 2;
#pragma unroll
    for (int mi = 0; mi < 4; mi++) {
#pragma unroll
        for (int half = 0; half < 2; half++) {
            int m = mBase + wm * 64 + mi * 16 + r_in + half * 8;
#pragma unroll
            for (int ni = 0; ni < 4; ni++) {
                int n = nBase + wn * 32 + ni * 8 + c_in;
                float v0 = acc[mi][ni][half * 2 + 0] + bias[n];
                float v1 = acc[mi][ni][half * 2 + 1] + bias[n + 1];
                if (MODE == 0) {
                    int b = m >> 12, t = m & 4095;
                    int sect = n >> 10, cc = n & 1023;
                    int head = cc >> 6, d0 = cc & 63;
                    size_t off = (((size_t)(b * NH + head)) * TSEQ + t) * HD + d0;
                    __half* dst = (sect == 0) ? g_q16 : (sect == 1) ? g_k16 : g_v16;
                    *(uint32_t*)&dst[off] = packh(v0, v1);
                } else {
                    *(float2*)&out[(size_t)m * CEMB + n] = make_float2(v0, v1);
                }
            }
        }
    }
}

// ---------------- fp16 HMMA block-sparse flash attention -----------------------
#define SMQ    0                            // 9216
#define SBA    9216
#define SLB    46080
#define SBGK   101376
#define SLAB   9216
#define SLABW  12288
#define SMRG   9216
#define MERGE_B 4352
#define ATTN_SM (SLAB + 8*SLABW)            // 107520

// MODE: 0 = fully valid, 1 = upper, 2 = lower, 3 = general
template <int NNI, int MODE>
__device__ __forceinline__ void dense_block(
    const uint32_t (&qf)[4][4], uint32_t kst, uint32_t vst, int lane, int rblk,
    int colbase, int i0, int jb, float (&oacc)[8][4], float (&m)[2], float (&l)[2])
{
    const int NKK = NNI / 2;
    int g = lane >> 3, w = lane & 7;
    uint32_t kboff = (g & 1) * 16;

    unsigned skipmask = 0;
    if (MODE == 1) {
#pragma unroll
        for (int ni = 0; ni < NNI; ni++)
            if (colbase + ni * 8 + 7 < rblk) skipmask |= 1u << ni;
    } else if (MODE == 2) {
#pragma unroll
        for (int ni = 0; ni < NNI; ni++)
            if (colbase + ni * 8 > rblk + 15) skipmask |= 1u << ni;
    }

    float sacc[NNI][4];
#pragma unroll
    for (int ni = 0; ni < NNI; ni++)
#pragma unroll
        for (int q = 0; q < 4; q++) sacc[ni][q] = 0.f;

#pragma unroll
    for (int ks = 0; ks < 4; ks++) {
#pragma unroll
        for (int ni = 0; ni < NNI; ni++) {
            if ((skipmask >> ni) & 1) continue;
            uint32_t kb2[2];
            ldmx2(kb2, kst + (colbase + ni * 8 + w) * 144 + kboff + ks * 32);
            mma16816(sacc[ni], qf[ks], kb2);
        }
    }

    int c0 = (lane & 3) * 2;
    float mb0 = -1e30f, mb1 = -1e30f;
#pragma unroll
    for (int ni = 0; ni < NNI; ni++) {
        if ((skipmask >> ni) & 1) continue;
        int jB = jb + ni * 8 + c0;
#pragma unroll
        for (int q = 0; q < 4; q++) {
            int jj = jB + (q & 1);
            int ii = (q < 2) ? i0 : i0 + 8;
            bool ok;
            if (MODE == 0) ok = true;
            else if (MODE == 1) ok = (ii - jj) <= 256;
            else if (MODE == 2) ok = jj <= ii;
            else {
                int diff = ii - jj;
                ok = diff >= 0 && (diff < 256 || (diff & 127) == 0 || jj < 16);
            }
            sacc[ni][q] = ok ? sacc[ni][q] * SCALE2 : -1e30f;
        }
        mb0 = fmaxf(mb0, fmaxf(sacc[ni][0], sacc[ni][1]));
        mb1 = fmaxf(mb1, fmaxf(sacc[ni][2], sacc[ni][3]));
    }
    mb0 = fmaxf(mb0, __shfl_xor_sync(0xffffffffu, mb0, 1));
    mb0 = fmaxf(mb0, __shfl_xor_sync(0xffffffffu, mb0, 2));
    mb1 = fmaxf(mb1, __shfl_xor_sync(0xffffffffu, mb1, 1));
    mb1 = fmaxf(mb1, __shfl_xor_sync(0xffffffffu, mb1, 2));

    float mn0 = fmaxf(fmaxf(m[0], mb0), -1e28f);
    float mn1 = fmaxf(fmaxf(m[1], mb1), -1e28f);
    bool up = __any_sync(0xffffffffu, (mn0 > m[0]) || (mn1 > m[1]));
    float cs0 = 1.f, cs1 = 1.f;
    if (up) { cs0 = ex2(m[0] - mn0); cs1 = ex2(m[1] - mn1); }

    uint32_t pp[NNI][2];
    float ls0 = 0.f, ls1 = 0.f;
#pragma unroll
    for (int ni = 0; ni < NNI; ni++) {
        if ((skipmask >> ni) & 1) { pp[ni][0] = 0u; pp[ni][1] = 0u; continue; }
        uint32_t a0 = packh(sacc[ni][0] - mn0, sacc[ni][1] - mn0);
        uint32_t a1 = packh(sacc[ni][2] - mn1, sacc[ni][3] - mn1);
        uint32_t p0 = ex2h2(a0), p1 = ex2h2(a1);
        pp[ni][0] = p0; pp[ni][1] = p1;
        float2 f0 = h2f2(p0), f1 = h2f2(p1);
        ls0 += f0.x + f0.y; ls1 += f1.x + f1.y;
    }
    ls0 += __shfl_xor_sync(0xffffffffu, ls0, 1);
    ls0 += __shfl_xor_sync(0xffffffffu, ls0, 2);
    ls1 += __shfl_xor_sync(0xffffffffu, ls1, 1);
    ls1 += __shfl_xor_sync(0xffffffffu, ls1, 2);
    if (up) {
        l[0] = l[0] * cs0 + ls0;
        l[1] = l[1] * cs1 + ls1;
#pragma unroll
        for (int nd = 0; nd < 8; nd++) {
            oacc[nd][0] *= cs0; oacc[nd][1] *= cs0;
            oacc[nd][2] *= cs1; oacc[nd][3] *= cs1;
        }
    } else {
        l[0] += ls0; l[1] += ls1;
    }
    m[0] = mn0; m[1] = mn1;

    int jrow = ((g & 1) << 3) + w;
    int dcol = (g >> 1) * 16;
#pragma unroll
    for (int kk = 0; kk < NKK; kk++) {
        if (((skipmask >> (2 * kk)) & 3u) == 3u) continue;
        uint32_t pa[4] = { pp[2*kk][0], pp[2*kk][1], pp[2*kk+1][0], pp[2*kk+1][1] };
#pragma unroll
        for (int gv = 0; gv < 2; gv++) {
            uint32_t vh4[2][4];
#pragma unroll
            for (int u = 0; u < 2; u++) {
                int nd2 = gv * 2 + u;
                ldmx4t(vh4[u], vst + (colbase + kk * 16 + jrow) * 144 + nd2 * 32 + dcol);
            }
#pragma unroll
            for (int u = 0; u < 2; u++) {
                int nd2 = gv * 2 + u;
                mma16816(oacc[nd2 * 2],     pa, vh4[u]);
                mma16816(oacc[nd2 * 2 + 1], pa, vh4[u] + 2);
            }
        }
    }
}

__global__ __launch_bounds__(256, 2)
void attn_mma()
{
    extern __shared__ __align__(16) char sm[];
    uint32_t smb = smem_u32(sm);
    int tid = threadIdx.x, lane = tid & 31, wid = tid >> 5;
    int rg = wid >> 1, ch2 = wid & 1;
    int qt = (gridDim.x - 1) - blockIdx.x;
    int qb = qt >> 1, s = qt & 1;
    int bh = blockIdx.y;

    auto stage_rows = [&](uint32_t dst, const __half* src, int nrows) {
        for (int c = tid; c < nrows * 8; c += 256) {
            int row = c >> 3, ch = c & 7;
            cpasync16(dst + row * 144 + ch * 16, src + (size_t)row * HD + ch * 8);
        }
    };
    size_t hb = (size_t)bh * TSEQ * HD;

    stage_rows(smb + SMQ, g_q16 + hb + (size_t)qt * 64 * HD, 64);

    float oacc[8][4];
#pragma unroll
    for (int nd = 0; nd < 8; nd++)
#pragma unroll
        for (int q = 0; q < 4; q++) oacc[nd][q] = 0.f;
    float m[2] = { -1e30f, -1e30f }, l[2] = { 0.f, 0.f };
    int lr0 = rg * 16;
    int rblk = s * 64 + lr0;
    int i0 = qt * 64 + lr0 + (lane >> 2);

    uint32_t qf[4][4];
    int gq = lane >> 3, wq_ = lane & 7;
    uint32_t qrow = smb + SMQ + (lr0 + ((gq & 1) << 3) + wq_) * 144 + (gq >> 1) * 16;

    if (qb >= 3) {
        stage_rows(smb + SBA,         g_k16 + hb + (size_t)(qb - 1) * 128 * HD, 128);
        stage_rows(smb + SBA + 18432, g_v16 + hb + (size_t)(qb - 1) * 128 * HD, 128);
        CP_COMMIT();
        int cminB = s ? 64 : 0, cntB = s ? 64 : 128;
        uint32_t bK = smb + SLB, bV = bK + (uint32_t)cntB * 144;
        stage_rows(bK, g_k16 + hb + ((size_t)(qb - 2) * 128 + cminB) * HD, cntB);
        stage_rows(bV, g_v16 + hb + ((size_t)(qb - 2) * 128 + cminB) * HD, cntB);
        CP_COMMIT();
        int cntC = s ? 128 : 64;
        uint32_t cK = bV + (uint32_t)cntB * 144, cV = cK + (uint32_t)cntC * 144;
        stage_rows(cK, g_k16 + hb + (size_t)qb * 128 * HD, cntC);
        stage_rows(cV, g_v16 + hb + (size_t)qb * 128 * HD, cntC);
        stage_rows(smb + SBGK,        g_k16 + hb, 16);
        stage_rows(smb + SBGK + 2304, g_v16 + hb, 16);
        CP_COMMIT();

        CP_WAIT2(); __syncthreads();
#pragma unroll
        for (int ks = 0; ks < 4; ks++) ldmx4(qf[ks], qrow + ks * 32);
        dense_block<8, 0>(qf, smb + SBA, smb + SBA + 18432, lane, rblk,
                          ch2 * 64, i0, (qb - 1) * 128 + ch2 * 64, oacc, m, l);
        CP_WAIT0(); __syncthreads();
        dense_block<8, 1>(qf, bK - (uint32_t)cminB * 144, bV - (uint32_t)cminB * 144,
                          lane, rblk, ch2 * 64, i0, (qb - 2) * 128 + ch2 * 64, oacc, m, l);
        dense_block<8, 2>(qf, cK, cV, lane, rblk,
                          ch2 * 64, i0, qb * 128 + ch2 * 64, oacc, m, l);
        if (ch2 == 0)
            dense_block<2, 0>(qf, smb + SBGK, smb + SBGK + 2304, lane, rblk,
                              0, i0, 0, oacc, m, l);
    } else {
        stage_rows(smb + SBA,         g_k16 + hb, 128);
        stage_rows(smb + SBA + 18432, g_v16 + hb, 128);
        CP_COMMIT();
        if (qb >= 1) {
            stage_rows(smb + SLB,         g_k16 + hb + (size_t)128 * HD, 128);
            stage_rows(smb + SLB + 18432, g_v16 + hb + (size_t)128 * HD, 128);
        }
        CP_COMMIT();
        if (qb >= 1) CP_WAIT1(); else CP_WAIT0();
        __syncthreads();
#pragma unroll
        for (int ks = 0; ks < 4; ks++) ldmx4(qf[ks], qrow + ks * 32);
        dense_block<8, 3>(qf, smb + SBA, smb + SBA + 18432, lane, rblk,
                          ch2 * 64, i0, ch2 * 64, oacc, m, l);
        if (qb >= 1) {
            CP_WAIT0();
            __syncthreads();
            if (qb >= 2) {
                stage_rows(smb + SBA,         g_k16 + hb + (size_t)256 * HD, 128);
                stage_rows(smb + SBA + 18432, g_v16 + hb + (size_t)256 * HD, 128);
                CP_COMMIT();
            }
            dense_block<8, 3>(qf, smb + SLB, smb + SLB + 18432, lane, rblk,
                              ch2 * 64, i0, 128 + ch2 * 64, oacc, m, l);
            if (qb >= 2) {
                CP_WAIT0(); __syncthreads();
                dense_block<8, 3>(qf, smb + SBA, smb + SBA + 18432, lane, rblk,
                                  ch2 * 64, i0, 256 + ch2 * 64, oacc, m, l);
            }
        }
    }

    // ---------- strided diagonals ----------
    int nkb = qb - 2;
    if (nkb > 0) {
        __syncthreads();
        uint32_t slab = smb + SLAB + wid * SLABW;
        int part = lane & 3, qr = lane >> 2;

        auto stage_kb = [&](int slot, int kb) {
            size_t rowbase = (size_t)kb * 128 + s * 64 + rg * 16;
            const __half* Ksrc = g_k16 + hb + rowbase * HD;
            const __half* Vsrc = g_v16 + hb + rowbase * HD;
            uint32_t base = slab + slot * 4096;
#pragma unroll
            for (int c = lane; c < 128; c += 32) {
                int row = c >> 3, ch = c & 7;
                cpasync16(base + row * 128 + ch * 16,
                          Ksrc + (size_t)row * HD + ch * 8);
                cpasync16(base + 2048 + row * 128 + ch * 16,
                          Vsrc + (size_t)row * HD + ch * 8);
            }
            CP_COMMIT();
        };

        int nexts = ch2;
#pragma unroll
        for (int st2 = 0; st2 < 3; st2++) {
            if (nexts < nkb) { stage_kb(st2, nexts); nexts += 2; }
        }

        int it = 0;
        for (int kb = ch2; kb < nkb; kb += 2, it++) {
            int ahead = (nexts - kb) >> 1;
            if (ahead >= 3) CP_WAIT2();
            else if (ahead == 2) CP_WAIT1();
            else CP_WAIT0();
            __syncwarp();

            uint32_t st = slab + (it % 3) * 4096;
#pragma unroll
            for (int h = 0; h < 2; h++) {
                int lr = qr + h * 8;
                int rowin128 = s * 64 + rg * 16 + lr;
                float sc;
                if (kb == 0 && rowin128 < 16) {
                    sc = -1e30f;
                } else {
                    uint32_t kaddr = st + lr * 128 + part * 32;
                    uint32_t qaddr = smb + SMQ + (rg * 16 + lr) * 144 + part * 32;
                    float sum = 0.f;
#pragma unroll
                    for (int seg = 0; seg < 2; seg++) {
                        uint32_t k4[4], q4[4];
                        asm volatile("ld.shared.v4.b32 {%0,%1,%2,%3}, [%4];"
                            : "=r"(k4[0]), "=r"(k4[1]), "=r"(k4[2]), "=r"(k4[3])
                            : "r"(kaddr + seg * 16));
                        asm volatile("ld.shared.v4.b32 {%0,%1,%2,%3}, [%4];"
                            : "=r"(q4[0]), "=r"(q4[1]), "=r"(q4[2]), "=r"(q4[3])
                            : "r"(qaddr + seg * 16));
#pragma unroll
                        for (int u = 0; u < 4; u++) {
                            float2 qf2 = h2f2(q4[u]), kf = h2f2(k4[u]);
                            sum += qf2.x * kf.x + qf2.y * kf.y;
                        }
                    }
                    sum += __shfl_xor_sync(0xffffffffu, sum, 1);
                    sum += __shfl_xor_sync(0xffffffffu, sum, 2);
                    sc = sum * SCALE2;
                }
                float mold = m[h];
                float mx = fmaxf(fmaxf(mold, sc), -1e28f);
                float p = ex2(sc - mx);
                if (__any_sync(0xffffffffu, mx > mold)) {
                    float cs = ex2(mold - mx);
                    l[h] = l[h] * cs + p;
                    m[h] = mx;
#pragma unroll
                    for (int nd = 0; nd < 8; nd++) {
                        oacc[nd][h * 2 + 0] *= cs;
                        oacc[nd][h * 2 + 1] *= cs;
                    }
                } else {
                    l[h] += p;
                }
                uint32_t vaddr = st + 2048 + lr * 128 + part * 4;
#pragma unroll
                for (int nd = 0; nd < 8; nd++) {
                    uint32_t vv;
                    asm volatile("ld.shared.b32 %0, [%1];"
                        : "=r"(vv) : "r"(vaddr + nd * 16));
                    float2 vf = h2f2(vv);
                    oacc[nd][h * 2 + 0] += p * vf.x;
                    oacc[nd][h * 2 + 1] += p * vf.y;
                }
            }

            if (nexts < nkb) {
                __syncwarp();
                stage_kb(it % 3, nexts);
                nexts += 2;
            }
        }
    }

    // pairwise split-softmax merge, then epilogue
    __syncthreads();
    {
        char* mb = sm + SMRG + wid * MERGE_B;
#pragma unroll
        for (int h = 0; h < 2; h++) {
            int row = (lane >> 2) + h * 8;
#pragma unroll
            for (int nd = 0; nd < 8; nd++) {
                int col = nd * 8 + (lane & 3) * 2;
                *(float2*)(mb + (row * 64 + col) * 4) =
                    make_float2(oacc[nd][h * 2], oacc[nd][h * 2 + 1]);
            }
            if ((lane & 3) == 0)
                *(float2*)(mb + 4096 + row * 8) = make_float2(m[h], l[h]);
        }
    }
    __syncthreads();
    if (ch2 == 0) {
        char* pb = sm + SMRG + (wid + 1) * MERGE_B;
        int b = bh >> 4, head = bh & 15;
#pragma unroll
        for (int h = 0; h < 2; h++) {
            int row = (lane >> 2) + h * 8;
            float2 ml = *(float2*)(pb + 4096 + row * 8);
            float mx = fmaxf(m[h], ml.x);
            float f0 = ex2(m[h] - mx), f1 = ex2(ml.x - mx);
            float L = l[h] * f0 + ml.y * f1;
            float inv = 1.f / L;
            int i = qt * 64 + rg * 16 + row;
            size_t row_off = ((size_t)(b * TSEQ + i)) * CEMB + head * HD;
#pragma unroll
            for (int nd = 0; nd < 8; nd++) {
                int col = nd * 8 + (lane & 3) * 2;
                float2 o1 = *(float2*)(pb + (row * 64 + col) * 4);
                float y0 = (oacc[nd][h * 2 + 0] * f0 + o1.x * f1) * inv;
                float y1 = (oacc[nd][h * 2 + 1] * f0 + o1.y * f1) * inv;
                *(uint32_t*)&g_y16[row_off + col] = packh(y0, y1);
            }
        }
    }
}

// ---------------- launch -------------------------------------------------------
extern "C" void kernel_launch(void* const* d_in, const int* in_sizes, int n_in,
                              void* d_out, int out_size)
{
    const float* x      = (const float*)d_in[0];
    const float* w_qkv  = (const float*)d_in[1];
    const float* b_qkv  = (const float*)d_in[2];
    const float* w_proj = (const float*)d_in[3];
    const float* b_proj = (const float*)d_in[4];
    float* out = (float*)d_out;

    cudaFuncSetAttribute(gemm_mma<0>,
                         cudaFuncAttributeMaxDynamicSharedMemorySize, GSMEM);
    cudaFuncSetAttribute(gemm_mma<1>,
                         cudaFuncAttributeMaxDynamicSharedMemorySize, GSMEM);
    cudaFuncSetAttribute(attn_mma,
                         cudaFuncAttributeMaxDynamicSharedMemorySize, ATTN_SM);

    conv_all<<<12288, 256>>>(x, w_qkv, w_proj);
    gemm_mma<0><<<dim3(3 * CEMB / 128, MROWS / 128), 256, GSMEM>>>(b_qkv, nullptr);
    attn_mma<<<dim3(TSEQ / 64, BATCH * NH), 256, ATTN_SM>>>();
    gemm_mma<1><<<dim3(CEMB / 128, MROWS / 128), 256, GSMEM>>>(b_proj, out);
}